// round 7
// baseline (speedup 1.0000x reference)
#include <cuda_runtime.h>

#define NB   4
#define NH   4
#define NN   2048
#define FIN  128
#define ND   32
#define BHD  (NB*NH)
#define NCH  16      // chunks per (b,h)
#define CHSZ 128     // rows per chunk

// scratch (device globals; no allocation allowed)
__device__ float  g_Wh  [BHD*NN*ND];
__device__ float  g_Wh1 [BHD*NN];
__device__ float  g_Wh2 [BHD*NN];
__device__ int    g_perm[BHD*NN];        // sorted pos -> original row
__device__ float  g_ewn [BHD*NN];        // exp(0.2*w2) in sorted order
__device__ float  g_ewp [BHD*NN];        // exp(w2) in sorted order
__device__ float  g_SnegL[BHD*NN*ND];    // per-chunk exclusive prefix of exp(.2 w2)*Wh
__device__ float  g_SposL[BHD*NN*ND];    // per-chunk inclusive suffix of exp(w2)*Wh
__device__ float  g_CnegT[BHD*NCH*ND];   // chunk total vectors
__device__ float  g_CposT[BHD*NCH*ND];
__device__ float  g_pn  [BHD*(NN+1)];    // GLOBAL scalar exclusive prefix (pn[NN]=total)
__device__ float  g_pp  [BHD*(NN+1)];    // GLOBAL scalar inclusive suffix (pp[NN]=0)
__device__ int    g_lo  [BHD*NN];        // per-row threshold position
__device__ float2 g_f12 [BHD*NN];        // (exp(w1), exp(0.2*w1))

__device__ __forceinline__ float warp_incl_scan(float v, int lane) {
    #pragma unroll
    for (int o = 1; o < 32; o <<= 1) {
        float u = __shfl_up_sync(0xffffffffu, v, o);
        if (lane >= o) v += u;
    }
    return v;
}

__device__ __forceinline__ unsigned long long pack2(float x, float y) {
    unsigned long long r;
    asm("mov.b64 %0, {%1, %2};" : "=l"(r) : "f"(x), "f"(y));
    return r;
}
__device__ __forceinline__ float2 unpack2(unsigned long long v) {
    float2 r;
    asm("mov.b64 {%0, %1}, %2;" : "=f"(r.x), "=f"(r.y) : "l"(v));
    return r;
}
__device__ __forceinline__ void ffma2(unsigned long long& d, unsigned long long a, unsigned long long b) {
    asm("fma.rn.f32x2 %0, %1, %2, %0;" : "+l"(d) : "l"(a), "l"(b));
}

// ---------------- kernel 1: Wh = x @ W[h] (in-block transpose + f32x2 register tile) ----
#define RS 132
#define SM1_X     (FIN*RS*4)
#define SM1_W     (FIN*ND*4)
#define SM1_BYTES (SM1_X + SM1_W + 256)

__global__ void __launch_bounds__(256) k1(const float* __restrict__ x,
                                          const float* __restrict__ W,
                                          const float* __restrict__ a) {
    extern __shared__ char sm1[];
    float* xsT = (float*)sm1;                       // [FIN][RS]
    float* Ws  = (float*)(sm1 + SM1_X);             // [FIN][ND]
    float* a1s = (float*)(sm1 + SM1_X + SM1_W);
    float* a2s = a1s + 32;

    const int h = blockIdx.y, b = blockIdx.z;
    const int n0 = blockIdx.x * 128;
    const int tid = threadIdx.x;

    for (int i = tid; i < FIN*ND; i += 256) Ws[i] = W[h*FIN*ND + i];
    if (tid < 64) {
        float v = a[h*2*ND + tid];
        if (tid < 32) a1s[tid] = v; else a2s[tid-32] = v;
    }
    {
        const int n = tid >> 1, kh = (tid & 1) * 64;
        const float* xr = x + ((size_t)(b*NN + n0 + n))*FIN + kh;
        #pragma unroll
        for (int q = 0; q < 16; q++) {
            float4 v = ((const float4*)xr)[q];
            const int k = kh + 4*q;
            xsT[(k+0)*RS + n] = v.x;
            xsT[(k+1)*RS + n] = v.y;
            xsT[(k+2)*RS + n] = v.z;
            xsT[(k+3)*RS + n] = v.w;
        }
    }
    __syncthreads();

    const int tx = tid & 7, ty = tid >> 3;
    const float* xp = xsT + 4*ty;
    const float* wp = Ws + 4*tx;

    unsigned long long acc[4][2];
    #pragma unroll
    for (int i = 0; i < 4; i++) { acc[i][0] = 0ull; acc[i][1] = 0ull; }

    #pragma unroll 8
    for (int k = 0; k < FIN; k++) {
        float4 xq = *(const float4*)(xp + (size_t)k*RS);
        ulonglong2 wq = *(const ulonglong2*)(wp + k*ND);
        unsigned long long x0 = pack2(xq.x, xq.x);
        unsigned long long x1 = pack2(xq.y, xq.y);
        unsigned long long x2 = pack2(xq.z, xq.z);
        unsigned long long x3 = pack2(xq.w, xq.w);
        ffma2(acc[0][0], x0, wq.x); ffma2(acc[0][1], x0, wq.y);
        ffma2(acc[1][0], x1, wq.x); ffma2(acc[1][1], x1, wq.y);
        ffma2(acc[2][0], x2, wq.x); ffma2(acc[2][1], x2, wq.y);
        ffma2(acc[3][0], x3, wq.x); ffma2(acc[3][1], x3, wq.y);
    }

    const int bh = b*NH + h;
    #pragma unroll
    for (int i = 0; i < 4; i++) {
        float2 p0 = unpack2(acc[i][0]);
        float2 p1 = unpack2(acc[i][1]);
        const int n = n0 + 4*ty + i;
        *(float4*)&g_Wh[((size_t)(bh*NN + n))*ND + 4*tx] = make_float4(p0.x, p0.y, p1.x, p1.y);

        float s1 = p0.x*a1s[4*tx+0] + p0.y*a1s[4*tx+1] + p1.x*a1s[4*tx+2] + p1.y*a1s[4*tx+3];
        float s2 = p0.x*a2s[4*tx+0] + p0.y*a2s[4*tx+1] + p1.x*a2s[4*tx+2] + p1.y*a2s[4*tx+3];
        #pragma unroll
        for (int o2 = 4; o2; o2 >>= 1) {
            s1 += __shfl_xor_sync(0xffffffffu, s1, o2);
            s2 += __shfl_xor_sync(0xffffffffu, s2, o2);
        }
        if (tx == 0) { g_Wh1[bh*NN + n] = s1; g_Wh2[bh*NN + n] = s2; }
    }
}

// ---------------- kernel 2: sort + exps + global scalar scans + searches ----------------
__global__ void __launch_bounds__(1024) k2sort() {
    __shared__ unsigned long long kv[NN];
    __shared__ float sA[NN];
    __shared__ float sB[NN];
    __shared__ float part[32];
    __shared__ float offs[33];
    const int bh = blockIdx.x;
    const int tid = threadIdx.x, warp = tid >> 5, lane = tid & 31;

    for (int e = tid; e < NN; e += 1024) {
        unsigned u = __float_as_uint(g_Wh2[bh*NN + e]);
        u = (u & 0x80000000u) ? ~u : (u | 0x80000000u);
        kv[e] = ((unsigned long long)u << 32) | (unsigned)e;
    }
    __syncthreads();

    for (int k = 2; k <= NN; k <<= 1) {
        int s = k >> 1;
        for (; s >= 32; s >>= 1) {
            #pragma unroll
            for (int tt = 0; tt < 2; tt++) {
                int t = tid + tt*1024;
                int j = t ^ s;
                if (j > t) {
                    unsigned long long va = kv[t], vb = kv[j];
                    bool up = ((t & k) == 0);
                    if ((va > vb) == up) { kv[t] = vb; kv[j] = va; }
                }
            }
            __syncthreads();
        }
        for (; s >= 1; s >>= 1) {
            #pragma unroll
            for (int tt = 0; tt < 2; tt++) {
                int t = tid + tt*1024;
                int j = t ^ s;
                if (j > t) {
                    unsigned long long va = kv[t], vb = kv[j];
                    bool up = ((t & k) == 0);
                    if ((va > vb) == up) { kv[t] = vb; kv[j] = va; }
                }
            }
            __syncwarp();
        }
        __syncthreads();
    }

    // exps + perm out
    for (int e = tid; e < NN; e += 1024) {
        unsigned long long v = kv[e];
        unsigned u = (unsigned)(v >> 32);
        u = (u & 0x80000000u) ? (u & 0x7fffffffu) : ~u;
        float f = __uint_as_float(u);
        float en = expf(0.2f * f), ep = expf(f);
        sA[e] = en; sB[e] = ep;
        g_ewn[bh*NN + e] = en;
        g_ewp[bh*NN + e] = ep;
        g_perm[bh*NN + e] = (int)(v & 0xffffffffu);
    }
    __syncthreads();

    // global exclusive prefix of sA (neg weights)
    {
        const int e0 = 64*warp + lane, e1 = e0 + 32;
        float a0 = sA[e0], a1 = sA[e1];
        float s0 = warp_incl_scan(a0, lane);
        float t0 = __shfl_sync(0xffffffffu, s0, 31);
        float s1 = warp_incl_scan(a1, lane);
        float seg = t0 + __shfl_sync(0xffffffffu, s1, 31);
        float x0 = __shfl_up_sync(0xffffffffu, s0, 1); if (lane == 0) x0 = 0.f;
        float x1 = __shfl_up_sync(0xffffffffu, s1, 1); if (lane == 0) x1 = 0.f;
        x1 += t0;
        if (lane == 0) part[warp] = seg;
        __syncthreads();
        if (warp == 0) {
            float sc = warp_incl_scan(part[lane], lane);
            float ex = __shfl_up_sync(0xffffffffu, sc, 1); if (lane == 0) ex = 0.f;
            offs[lane] = ex;
            if (lane == 31) offs[32] = sc;
        }
        __syncthreads();
        float off = offs[warp];
        g_pn[bh*(NN+1) + e0] = x0 + off;
        g_pn[bh*(NN+1) + e1] = x1 + off;
        if (tid == 0) g_pn[bh*(NN+1) + NN] = offs[32];
    }
    __syncthreads();

    // global inclusive suffix of sB (pos weights)
    {
        const int e0 = 64*warp + 63 - lane;   // descending within segment
        const int e1 = 64*warp + 31 - lane;
        float a0 = sB[e0], a1 = sB[e1];
        float s0 = warp_incl_scan(a0, lane);          // suffix incl at e0
        float t0 = __shfl_sync(0xffffffffu, s0, 31);
        float s1 = warp_incl_scan(a1, lane) + t0;     // suffix incl at e1
        float seg = __shfl_sync(0xffffffffu, s1, 31);
        if (lane == 0) part[warp] = seg;
        __syncthreads();
        if (warp == 0) {
            float sc = warp_incl_scan(part[31 - lane], lane);   // sum part[31-lane..31]
            float ex = __shfl_up_sync(0xffffffffu, sc, 1); if (lane == 0) ex = 0.f;
            offs[31 - lane] = ex;                               // sum part[w+1..31]
        }
        __syncthreads();
        float off = offs[warp];
        g_pp[bh*(NN+1) + e0] = s0 + off;
        g_pp[bh*(NN+1) + e1] = s1 + off;
        if (tid == 0) g_pp[bh*(NN+1) + NN] = 0.f;
    }
    __syncthreads();

    // all per-row threshold searches in smem keys + exp factors
    #pragma unroll
    for (int t = 0; t < 2; t++) {
        const int i = tid + t*1024;
        float w1 = g_Wh1[bh*NN + i];
        float thr = -w1;
        unsigned ut = __float_as_uint(thr);
        ut = (ut & 0x80000000u) ? ~ut : (ut | 0x80000000u);
        int lo = 0, hi = NN;
        #pragma unroll
        for (int it = 0; it < 11; it++) {
            int mid = (lo + hi) >> 1;
            if (mid < hi) { if ((unsigned)(kv[mid] >> 32) <= ut) lo = mid + 1; else hi = mid; }
        }
        g_lo[bh*NN + i] = lo;
        g_f12[bh*NN + i] = make_float2(expf(w1), expf(0.2f * w1));
    }
}

// ---------------- kernel 3: per-chunk vector scans + chunk totals ----------------
#define SM3_T     (CHSZ*(ND+1)*4)
#define SM3_BYTES (3*SM3_T + CHSZ*4*2 + CHSZ*4)

__global__ void __launch_bounds__(1024) k3() {
    extern __shared__ char sm3[];
    float (*tA )[ND+1] = (float(*)[ND+1])sm3;
    float (*tBn)[ND+1] = (float(*)[ND+1])(sm3 + SM3_T);
    float (*tBp)[ND+1] = (float(*)[ND+1])(sm3 + 2*SM3_T);
    float* ewn = (float*)(sm3 + 3*SM3_T);
    float* ewp = ewn + CHSZ;
    int*   pr  = (int*)(ewp + CHSZ);

    const int c = blockIdx.x, bh = blockIdx.y;
    const int tid = threadIdx.x, warp = tid >> 5, lane = tid & 31;
    const int base = bh*NN + c*CHSZ;

    if (tid < CHSZ) {
        ewn[tid] = g_ewn[base + tid];
        ewp[tid] = g_ewp[base + tid];
        pr[tid]  = g_perm[base + tid];
    }
    __syncthreads();
    #pragma unroll
    for (int q = 0; q < 4; q++) {
        int r = warp + q*32;
        tA[r][lane] = g_Wh[((size_t)(bh*NN) + pr[r])*ND + lane];
    }
    __syncthreads();

    {
        float carry = 0.f;
        #pragma unroll
        for (int s = 0; s < 4; s++) {
            int j = s*32 + lane;
            float v = ewn[j] * tA[j][warp];
            float inc = warp_incl_scan(v, lane);
            float exc = __shfl_up_sync(0xffffffffu, inc, 1);
            if (lane == 0) exc = 0.f;
            tBn[j][warp] = carry + exc;
            carry += __shfl_sync(0xffffffffu, inc, 31);
        }
        if (lane == 0) g_CnegT[(bh*NCH + c)*ND + warp] = carry;
    }
    {
        float carry = 0.f;
        #pragma unroll
        for (int s = 3; s >= 0; s--) {
            int j = s*32 + (31 - lane);
            float v = ewp[j] * tA[j][warp];
            float inc = warp_incl_scan(v, lane);
            tBp[j][warp] = carry + inc;
            carry += __shfl_sync(0xffffffffu, inc, 31);
        }
        if (lane == 0) g_CposT[(bh*NCH + c)*ND + warp] = carry;
    }
    __syncthreads();
    #pragma unroll
    for (int q = 0; q < 4; q++) {
        int r = warp + q*32;
        g_SnegL[((size_t)base + r)*ND + lane] = tBn[r][lane];
        g_SposL[((size_t)base + r)*ND + lane] = tBp[r][lane];
    }
}

// ---------------- kernel 5: streaming combine (64 rows/block, 512 blocks) ----------------
__global__ void __launch_bounds__(256) k5f(float* __restrict__ out) {
    __shared__ float cn[NCH*ND], cp[NCH*ND];
    __shared__ float OffN[(NCH+1)*ND], OffP[NCH*ND];
    const int seg = blockIdx.x, bh = blockIdx.y;
    const int b = bh >> 2, h = bh & 3;
    const int tid = threadIdx.x, warp = tid >> 5, lane = tid & 31;

    for (int j = tid; j < NCH*ND; j += 256) {
        cn[j] = g_CnegT[bh*NCH*ND + j];
        cp[j] = g_CposT[bh*NCH*ND + j];
    }
    __syncthreads();
    if (warp == 0) {
        float s = 0.f;
        #pragma unroll
        for (int c = 0; c < NCH; c++) { OffN[c*ND + lane] = s; s += cn[c*ND + lane]; }
        OffN[NCH*ND + lane] = s;
    } else if (warp == 1) {
        float s = 0.f;
        #pragma unroll
        for (int c = NCH-1; c >= 0; c--) { OffP[c*ND + lane] = s; s += cp[c*ND + lane]; }
    }
    __syncthreads();

    const int i0 = seg*64 + warp*8;
    int lo_l = 0; float f1_l = 0.f, f2_l = 0.f;
    if (lane < 8) {
        lo_l = g_lo[bh*NN + i0 + lane];
        float2 f = g_f12[bh*NN + i0 + lane];
        f1_l = f.x; f2_l = f.y;
    }

    #pragma unroll
    for (int r = 0; r < 8; r++) {
        const int lo = __shfl_sync(0xffffffffu, lo_l, r);
        const float f1 = __shfl_sync(0xffffffffu, f1_l, r);
        const float f2 = __shfl_sync(0xffffffffu, f2_l, r);
        const int i = i0 + r;
        const float pn = g_pn[bh*(NN+1) + lo];
        const float pp = g_pp[bh*(NN+1) + lo];
        float sneg, spos;
        if (lo < NN) {
            const int c = lo >> 7;
            const size_t ix = ((size_t)(bh*NN) + lo)*ND + lane;
            sneg = g_SnegL[ix] + OffN[c*ND + lane];
            spos = g_SposL[ix] + OffP[c*ND + lane];
        } else {
            sneg = OffN[NCH*ND + lane];
            spos = 0.f;
        }
        float num = f2*sneg + f1*spos;
        float den = f2*pn + f1*pp;
        float hv = num / den;
        float res = hv > 0.f ? hv : expm1f(hv);
        out[((size_t)(b*NN + i))*(NH*ND) + h*ND + lane] = res;
    }
}

extern "C" void kernel_launch(void* const* d_in, const int* in_sizes, int n_in,
                              void* d_out, int out_size) {
    (void)in_sizes; (void)n_in; (void)out_size;
    const float* x = (const float*)d_in[0];
    const float* W = (const float*)d_in[1];
    const float* a = (const float*)d_in[2];
    float* out = (float*)d_out;

    static int attr_set = 0;
    if (!attr_set) {
        cudaFuncSetAttribute(k1, cudaFuncAttributeMaxDynamicSharedMemorySize, SM1_BYTES);
        cudaFuncSetAttribute(k3, cudaFuncAttributeMaxDynamicSharedMemorySize, SM3_BYTES);
        attr_set = 1;
    }

    k1<<<dim3(NN/128, NH, NB), 256, SM1_BYTES>>>(x, W, a);
    k2sort<<<BHD, 1024>>>();
    k3<<<dim3(NCH, BHD), 1024, SM3_BYTES>>>();
    k5f<<<dim3(NN/64, BHD), 256>>>(out);
}